// round 2
// baseline (speedup 1.0000x reference)
#include <cuda_runtime.h>

#define NW 12
#define NL 3
#define DIM 4096
#define NT 256
#define NGROUP (DIM / 4)     /* 1024 four-amplitude groups per pass */
#define GPT (NGROUP / NT)    /* 4 groups per thread */

__device__ __forceinline__ unsigned ins0(unsigned v, int p) {
    // insert a zero bit at position p
    return ((v >> p) << (p + 1)) | (v & ((1u << p) - 1u));
}

__device__ __forceinline__ float2 cmul2(float2 u, float2 s) {
    return make_float2(u.x * s.x - u.y * s.y, u.x * s.y + u.y * s.x);
}
__device__ __forceinline__ void cmac(float2 u, float2 s, float2& a) {
    a.x = fmaf(u.x, s.x, fmaf(-u.y, s.y, a.x));
    a.y = fmaf(u.x, s.y, fmaf(u.y, s.x, a.y));
}

__global__ __launch_bounds__(NT)
void qsim_kernel(const float* __restrict__ state,
                 const float* __restrict__ wts,
                 const float* __restrict__ head_w,
                 const float* __restrict__ head_b,
                 float* __restrict__ out)
{
    __shared__ float2 psi[DIM];            // 32 KB state
    __shared__ float2 G[NL * NW][4];       // 36 fused RZ*RY*RX 2x2 complex gates
    __shared__ unsigned fcol_s[NW];        // columns of phi   (logical->physical XOR masks)
    __shared__ unsigned rinv_s[NW];        // rows of phi^-1   (physical->logical bit parities)
    __shared__ float red[NT / 32];

    const int tid = threadIdx.x;
    const int b = blockIdx.x;

    // ---- load initial (real) state: psi = state + 0i ----
    {
        const float4* s4 = (const float4*)(state + (size_t)b * DIM);
        #pragma unroll
        for (int j = 0; j < DIM / 4 / NT; ++j) {
            int i = tid + j * NT;
            float4 v = s4[i];
            psi[4 * i + 0] = make_float2(v.x, 0.f);
            psi[4 * i + 1] = make_float2(v.y, 0.f);
            psi[4 * i + 2] = make_float2(v.z, 0.f);
            psi[4 * i + 3] = make_float2(v.w, 0.f);
        }
    }

    // ---- build gate matrices: U = RZ(c) RY(b) RX(a) ----
    if (tid < NL * NW) {
        float a  = wts[tid * 3 + 0] * 0.5f;
        float bb = wts[tid * 3 + 1] * 0.5f;
        float c  = wts[tid * 3 + 2] * 0.5f;
        float ca, sa, cb, sb, cc, sc;
        sincosf(a, &sa, &ca);
        sincosf(bb, &sb, &cb);
        sincosf(c, &sc, &cc);
        // M = RY @ RX
        float m00x = cb * ca, m00y =  sb * sa;
        float m01x = -sb * ca, m01y = -cb * sa;
        float m10x =  sb * ca, m10y = -cb * sa;
        float m11x =  cb * ca, m11y = -sb * sa;
        // row0 *= e^{-ic/2} = (cc,-sc); row1 *= e^{+ic/2} = (cc,sc)
        G[tid][0] = make_float2(cc * m00x + sc * m00y, cc * m00y - sc * m00x);
        G[tid][1] = make_float2(cc * m01x + sc * m01y, cc * m01y - sc * m01x);
        G[tid][2] = make_float2(cc * m10x - sc * m10y, cc * m10y + sc * m10x);
        G[tid][3] = make_float2(cc * m11x - sc * m11y, cc * m11y + sc * m11x);
    }
    if (tid < NW) {
        fcol_s[tid] = 1u << tid;
        rinv_s[tid] = 1u << tid;
    }
    __syncthreads();

    // ---- 3 layers: 6 fused double-rotation passes each; CNOT chain folded into phi ----
    for (int l = 0; l < NL; ++l) {
        for (int d = 0; d < 6; ++d) {
            const int w1 = 2 * d, w0 = 2 * d + 1;            // wire indices
            const int k1 = NW - 1 - w1, k0 = NW - 1 - w0;    // logical bit positions
            // A acts on bit k0 (wire w0), B acts on bit k1 (wire w1)
            const float2 A00 = G[l * NW + w0][0], A01 = G[l * NW + w0][1];
            const float2 A10 = G[l * NW + w0][2], A11 = G[l * NW + w0][3];
            const float2 B00 = G[l * NW + w1][0], B01 = G[l * NW + w1][1];
            const float2 B10 = G[l * NW + w1][2], B11 = G[l * NW + w1][3];
            const unsigned m1 = fcol_s[k1], m0 = fcol_s[k0];
            const unsigned r1 = rinv_s[k1], r0 = rinv_s[k0];

            const int p1 = 31 - __clz((int)m1);
            const unsigned m0a = ((m0 >> p1) & 1u) ? (m0 ^ m1) : m0;
            const int p0 = 31 - __clz((int)m0a);
            const int pLo = p0 < p1 ? p0 : p1;
            const int pHi = p0 < p1 ? p1 : p0;

            #pragma unroll
            for (int j = 0; j < GPT; ++j) {
                const unsigned q = tid + j * NT;
                const unsigned y  = ins0(ins0(q, pLo), pHi);
                const unsigned e1 = y ^ m0a;
                const unsigned e2 = y ^ m1;
                const unsigned e3 = e1 ^ m1;

                float2 v0 = psi[y], v1 = psi[e1], v2 = psi[e2], v3 = psi[e3];
                const int t0 = __popc(r0 & y) & 1;   // logical bit k0 of slot y
                const int t1 = __popc(r1 & y) & 1;   // logical bit k1 of slot y
                if (t0) { float2 t = v0; v0 = v1; v1 = t; t = v2; v2 = v3; v3 = t; }
                if (t1) { float2 t = v0; v0 = v2; v2 = t; t = v1; v1 = v3; v3 = t; }

                // stage A on bit k0: pairs (v0,v1), (v2,v3)
                float2 s0 = cmul2(A00, v0); cmac(A01, v1, s0);
                float2 s1 = cmul2(A10, v0); cmac(A11, v1, s1);
                float2 s2 = cmul2(A00, v2); cmac(A01, v3, s2);
                float2 s3 = cmul2(A10, v2); cmac(A11, v3, s3);
                // stage B on bit k1: pairs (s0,s2), (s1,s3)
                float2 o0 = cmul2(B00, s0); cmac(B01, s2, o0);
                float2 o2 = cmul2(B10, s0); cmac(B11, s2, o2);
                float2 o1 = cmul2(B00, s1); cmac(B01, s3, o1);
                float2 o3 = cmul2(B10, s1); cmac(B11, s3, o3);

                if (t1) { float2 t = o0; o0 = o2; o2 = t; t = o1; o1 = o3; o3 = t; }
                if (t0) { float2 t = o0; o0 = o1; o1 = t; t = o2; o2 = o3; o3 = t; }
                psi[y] = o0; psi[e1] = o1; psi[e2] = o2; psi[e3] = o3;
            }
            __syncthreads();
        }
        // fold this layer's CNOT chain (x -> x ^ (x>>1)) into phi: phi' = phi o C
        if (tid == 0) {
            for (int k = NW - 1; k >= 1; --k) fcol_s[k] ^= fcol_s[k - 1];
            for (int k = NW - 2; k >= 0; --k) rinv_s[k] ^= rinv_s[k + 1];
        }
        __syncthreads();
    }

    // ---- fused <Z_w> expvals + linear head:
    //      out[b] = sum_i |psi_i|^2 * sum_w hw[w]*(+1/-1 per logical bit) + hb ----
    float h[NW];
    unsigned rv[NW];
    #pragma unroll
    for (int w = 0; w < NW; ++w) h[w] = head_w[w];
    #pragma unroll
    for (int k = 0; k < NW; ++k) rv[k] = rinv_s[k];

    float acc = 0.f;
    #pragma unroll
    for (int j = 0; j < DIM / NT; ++j) {
        const unsigned i = tid + j * NT;
        const float2 v = psi[i];
        const float p = v.x * v.x + v.y * v.y;
        float cf = 0.f;
        #pragma unroll
        for (int w = 0; w < NW; ++w) {
            cf += (__popc(rv[NW - 1 - w] & i) & 1) ? -h[w] : h[w];
        }
        acc = fmaf(p, cf, acc);
    }
    #pragma unroll
    for (int o = 16; o; o >>= 1) acc += __shfl_xor_sync(0xffffffffu, acc, o);
    if ((tid & 31) == 0) red[tid >> 5] = acc;
    __syncthreads();
    if (tid == 0) {
        float tot = 0.f;
        #pragma unroll
        for (int i = 0; i < NT / 32; ++i) tot += red[i];
        out[b] = tot + head_b[0];
    }
}

extern "C" void kernel_launch(void* const* d_in, const int* in_sizes, int n_in,
                              void* d_out, int out_size) {
    const float* state  = (const float*)d_in[0];   // (512, 4096) f32
    const float* wts    = (const float*)d_in[1];   // (3, 12, 3)  f32
    const float* head_w = (const float*)d_in[2];   // (1, 12)     f32
    const float* head_b = (const float*)d_in[3];   // (1,)        f32
    float* out = (float*)d_out;                    // (512,)      f32
    const int B = in_sizes[0] / DIM;
    qsim_kernel<<<B, NT>>>(state, wts, head_w, head_b, out);
}

// round 6
// speedup vs baseline: 1.6908x; 1.6908x over previous
#include <cuda_runtime.h>

#define NW 12
#define NL 3
#define DIM 4096
#define NT 256

// ---------------- compile-time GF(2) bookkeeping ----------------
struct Phi { unsigned f[NW]; unsigned r[NW]; };
__host__ __device__ constexpr Phi phi_after(int l) {
    Phi p{};
    for (int k = 0; k < NW; k++) { p.f[k] = 1u << k; p.r[k] = 1u << k; }
    for (int t = 0; t < l; t++) {
        for (int k = NW - 1; k >= 1; --k) p.f[k] ^= p.f[k - 1];
        for (int k = NW - 2; k >= 0; --k) p.r[k] ^= p.r[k + 1];
    }
    return p;
}
__host__ __device__ constexpr int msb_c(unsigned x) { int r = 0; while (x > 1u) { x >>= 1; ++r; } return r; }
struct Piv { int q0, q1, q2; };
__host__ __device__ constexpr Piv pivots3(unsigned a, unsigned b, unsigned c) {
    unsigned u[3] = {a, b, c};
    int pv[3] = {0, 0, 0};
    for (int i = 0; i < 3; i++) {
        int best = i, bm = msb_c(u[i]);
        for (int j = i + 1; j < 3; j++) { int m = msb_c(u[j]); if (m > bm) { bm = m; best = j; } }
        unsigned tmp = u[i]; u[i] = u[best]; u[best] = tmp;
        pv[i] = bm;
        for (int j = 0; j < 3; j++) if (j != i && ((u[j] >> bm) & 1u)) u[j] ^= u[i];
    }
    int q[3] = {pv[0], pv[1], pv[2]};
    for (int i = 0; i < 3; i++)
        for (int j = i + 1; j < 3; j++)
            if (q[j] < q[i]) { int t = q[i]; q[i] = q[j]; q[j] = t; }
    return Piv{q[0], q[1], q[2]};
}
__device__ __forceinline__ unsigned ins0(unsigned v, int p) {
    return ((v >> p) << (p + 1)) | (v & ((1u << p) - 1u));
}

// ---------------- f32x2 packed helpers (double = opaque 2xf32 carrier) ----------------
__device__ __forceinline__ double pk(float v) {
    double d; asm("mov.b64 %0, {%1, %1};" : "=d"(d) : "f"(v)); return d;
}
__device__ __forceinline__ double pk2(float a, float b) {
    double d; asm("mov.b64 %0, {%1, %2};" : "=d"(d) : "f"(a), "f"(b)); return d;
}
__device__ __forceinline__ double f2fma(double a, double b, double c) {
    double d; asm("fma.rn.f32x2 %0, %1, %2, %3;" : "=d"(d) : "d"(a), "d"(b), "d"(c)); return d;
}
__device__ __forceinline__ double f2mul(double a, double b) {
    double d; asm("mul.rn.f32x2 %0, %1, %2;" : "=d"(d) : "d"(a), "d"(b)); return d;
}
__device__ __forceinline__ double f2add(double a, double b) {
    double d; asm("add.rn.f32x2 %0, %1, %2;" : "=d"(d) : "d"(a), "d"(b)); return d;
}

// out0 = U00*a + U01*b ; out1 = U10*a + U11*b (complex, both f32x2 lanes = 2 batches)
// g layout per gate: [x00,-y00,y00, x01,-y01,y01, x10,-y10,y10, x11,-y11,y11]
__device__ __forceinline__ void apply_pair(const double* __restrict__ g, double2& A, double2& B) {
    double ar = A.x, ai = A.y, br = B.x, bi = B.y;
    double o0r = f2fma(g[0], ar, f2fma(g[1], ai, f2fma(g[3], br, f2mul(g[4], bi))));
    double o0i = f2fma(g[0], ai, f2fma(g[2], ar, f2fma(g[3], bi, f2mul(g[5], br))));
    double o1r = f2fma(g[6], ar, f2fma(g[7], ai, f2fma(g[9], br, f2mul(g[10], bi))));
    double o1i = f2fma(g[6], ai, f2fma(g[8], ar, f2fma(g[9], bi, f2mul(g[11], br))));
    A.x = o0r; A.y = o0i; B.x = o1r; B.y = o1i;
}

// 3-wire fused pass for layer L, wires W0..W0+2. All masks compile-time.
template <int L, int W0>
__device__ __forceinline__ void pass3(double2* __restrict__ s,
                                      const double* __restrict__ G2, int tid) {
    constexpr Phi P = phi_after(L);
    constexpr unsigned m0 = P.f[NW - 1 - W0];
    constexpr unsigned m1 = P.f[NW - 2 - W0];
    constexpr unsigned m2 = P.f[NW - 3 - W0];
    constexpr unsigned r0 = P.r[NW - 1 - W0];
    constexpr unsigned r1 = P.r[NW - 2 - W0];
    constexpr unsigned r2 = P.r[NW - 3 - W0];
    constexpr Piv PV = pivots3(m0, m1, m2);
    const double* gA = G2 + (L * NW + W0) * 12;
    const double* gB = gA + 12;
    const double* gC = gA + 24;

    #pragma unroll
    for (int j = 0; j < 2; ++j) {
        const unsigned t = tid + j * NT;
        const unsigned y = ins0(ins0(ins0(t, PV.q0), PV.q1), PV.q2);
        unsigned z = y;
        z ^= (__popc(r0 & y) & 1) ? m0 : 0u;
        z ^= (__popc(r1 & y) & 1) ? m1 : 0u;
        z ^= (__popc(r2 & y) & 1) ? m2 : 0u;

        double2 v0 = s[z];
        double2 v1 = s[z ^ m0];
        double2 v2 = s[z ^ m1];
        double2 v3 = s[z ^ (m1 ^ m0)];
        double2 v4 = s[z ^ m2];
        double2 v5 = s[z ^ (m2 ^ m0)];
        double2 v6 = s[z ^ (m2 ^ m1)];
        double2 v7 = s[z ^ (m2 ^ m1 ^ m0)];

        {   // stage: wire W0 (logical bit NW-1-W0) -> pairs along b0
            double g[12];
            #pragma unroll
            for (int i = 0; i < 12; i++) g[i] = gA[i];
            apply_pair(g, v0, v1); apply_pair(g, v2, v3);
            apply_pair(g, v4, v5); apply_pair(g, v6, v7);
        }
        {   // stage: wire W0+1 -> pairs along b1
            double g[12];
            #pragma unroll
            for (int i = 0; i < 12; i++) g[i] = gB[i];
            apply_pair(g, v0, v2); apply_pair(g, v1, v3);
            apply_pair(g, v4, v6); apply_pair(g, v5, v7);
        }
        {   // stage: wire W0+2 -> pairs along b2
            double g[12];
            #pragma unroll
            for (int i = 0; i < 12; i++) g[i] = gC[i];
            apply_pair(g, v0, v4); apply_pair(g, v1, v5);
            apply_pair(g, v2, v6); apply_pair(g, v3, v7);
        }

        s[z] = v0;
        s[z ^ m0] = v1;
        s[z ^ m1] = v2;
        s[z ^ (m1 ^ m0)] = v3;
        s[z ^ m2] = v4;
        s[z ^ (m2 ^ m0)] = v5;
        s[z ^ (m2 ^ m1)] = v6;
        s[z ^ (m2 ^ m1 ^ m0)] = v7;
    }
    __syncthreads();
}

__global__ __launch_bounds__(NT, 2)
void qsim_kernel(const float* __restrict__ state,
                 const float* __restrict__ wts,
                 const float* __restrict__ head_w,
                 const float* __restrict__ head_b,
                 float* __restrict__ out)
{
    extern __shared__ double2 s[];            // DIM amps: (re_b0,re_b1),(im_b0,im_b1)  64 KB
    __shared__ double G2s[NL * NW * 12];      // packed gate coefficients
    __shared__ double wred[NT / 32];

    const int tid = threadIdx.x;
    const int b = blockIdx.x;                 // handles batches 2b, 2b+1

    // ---- load two real input states, interleave into f32x2 lanes ----
    {
        const float4* ra = (const float4*)(state + (size_t)(2 * b) * DIM);
        const float4* rb = (const float4*)(state + (size_t)(2 * b + 1) * DIM);
        #pragma unroll
        for (int j = 0; j < DIM / 4 / NT; ++j) {
            int i4 = tid + j * NT;
            float4 xa = ra[i4];
            float4 xb = rb[i4];
            s[4 * i4 + 0] = make_double2(pk2(xa.x, xb.x), 0.0);
            s[4 * i4 + 1] = make_double2(pk2(xa.y, xb.y), 0.0);
            s[4 * i4 + 2] = make_double2(pk2(xa.z, xb.z), 0.0);
            s[4 * i4 + 3] = make_double2(pk2(xa.w, xb.w), 0.0);
        }
    }

    // ---- build fused U = RZ(c) RY(b) RX(a), store broadcast-packed ----
    if (tid < NL * NW) {
        float a  = wts[tid * 3 + 0] * 0.5f;
        float bb = wts[tid * 3 + 1] * 0.5f;
        float c  = wts[tid * 3 + 2] * 0.5f;
        float ca, sa, cb, sb, cc, sc;
        sincosf(a, &sa, &ca);
        sincosf(bb, &sb, &cb);
        sincosf(c, &sc, &cc);
        // M = RY @ RX
        float m00x =  cb * ca, m00y =  sb * sa;
        float m01x = -sb * ca, m01y = -cb * sa;
        float m10x =  sb * ca, m10y = -cb * sa;
        float m11x =  cb * ca, m11y = -sb * sa;
        // row0 *= (cc,-sc); row1 *= (cc,sc)
        float e00x = cc * m00x + sc * m00y, e00y = cc * m00y - sc * m00x;
        float e01x = cc * m01x + sc * m01y, e01y = cc * m01y - sc * m01x;
        float e10x = cc * m10x - sc * m10y, e10y = cc * m10y + sc * m10x;
        float e11x = cc * m11x - sc * m11y, e11y = cc * m11y + sc * m11x;
        double* gp = G2s + tid * 12;
        gp[0]  = pk(e00x); gp[1]  = pk(-e00y); gp[2]  = pk(e00y);
        gp[3]  = pk(e01x); gp[4]  = pk(-e01y); gp[5]  = pk(e01y);
        gp[6]  = pk(e10x); gp[7]  = pk(-e10y); gp[8]  = pk(e10y);
        gp[9]  = pk(e11x); gp[10] = pk(-e11y); gp[11] = pk(e11y);
    }
    __syncthreads();

    // ---- 3 layers x 4 fused 3-wire passes; CNOT chains folded into constexpr phi ----
    pass3<0, 0>(s, G2s, tid); pass3<0, 3>(s, G2s, tid);
    pass3<0, 6>(s, G2s, tid); pass3<0, 9>(s, G2s, tid);
    pass3<1, 0>(s, G2s, tid); pass3<1, 3>(s, G2s, tid);
    pass3<1, 6>(s, G2s, tid); pass3<1, 9>(s, G2s, tid);
    pass3<2, 0>(s, G2s, tid); pass3<2, 3>(s, G2s, tid);
    pass3<2, 6>(s, G2s, tid); pass3<2, 9>(s, G2s, tid);

    // ---- fused <Z_w> + linear head: out = sum_i |psi_i|^2 * cf(i) + bias ----
    constexpr Phi PF = phi_after(NL);
    float h[NW];
    #pragma unroll
    for (int w = 0; w < NW; ++w) h[w] = head_w[w];

    double acc = 0.0;   // packed (0,0)
    #pragma unroll
    for (int j = 0; j < DIM / NT; ++j) {
        const unsigned i = tid + j * NT;
        double2 v = s[i];
        double p2 = f2fma(v.x, v.x, f2mul(v.y, v.y));
        float cf = 0.f;
        #pragma unroll
        for (int w = 0; w < NW; ++w) {
            cf += (__popc(PF.r[NW - 1 - w] & i) & 1) ? -h[w] : h[w];
        }
        acc = f2fma(p2, pk(cf), acc);
    }
    #pragma unroll
    for (int o = 16; o; o >>= 1)
        acc = f2add(acc, __shfl_xor_sync(0xffffffffu, acc, o));
    if ((tid & 31) == 0) wred[tid >> 5] = acc;
    __syncthreads();
    if (tid == 0) {
        double tot = 0.0;
        #pragma unroll
        for (int i = 0; i < NT / 32; ++i) tot = f2add(tot, wred[i]);
        float lo, hi;
        asm("mov.b64 {%0, %1}, %2;" : "=f"(lo), "=f"(hi) : "d"(tot));
        float hb = head_b[0];
        out[2 * b + 0] = lo + hb;
        out[2 * b + 1] = hi + hb;
    }
}

extern "C" void kernel_launch(void* const* d_in, const int* in_sizes, int n_in,
                              void* d_out, int out_size) {
    const float* state  = (const float*)d_in[0];   // (512, 4096) f32
    const float* wts    = (const float*)d_in[1];   // (3, 12, 3)  f32
    const float* head_w = (const float*)d_in[2];   // (1, 12)     f32
    const float* head_b = (const float*)d_in[3];   // (1,)        f32
    float* out = (float*)d_out;                    // (512,)      f32

    const int B = in_sizes[0] / DIM;               // 512
    const int grid = B / 2;                        // 2 batches per block
    const int smem = DIM * sizeof(double2);        // 64 KB dynamic

    cudaFuncSetAttribute(qsim_kernel, cudaFuncAttributeMaxDynamicSharedMemorySize, smem);
    qsim_kernel<<<grid, NT, smem>>>(state, wts, head_w, head_b, out);
}

// round 8
// speedup vs baseline: 2.1614x; 1.2783x over previous
#include <cuda_runtime.h>

#define NW 12
#define NL 3
#define DIM 4096
#define NT 256

// ---------------- compile-time GF(2) bookkeeping ----------------
struct Phi { unsigned f[NW]; unsigned r[NW]; };
__host__ __device__ constexpr Phi phi_after(int l) {
    Phi p{};
    for (int k = 0; k < NW; k++) { p.f[k] = 1u << k; p.r[k] = 1u << k; }
    for (int t = 0; t < l; t++) {
        for (int k = NW - 1; k >= 1; --k) p.f[k] ^= p.f[k - 1];
        for (int k = NW - 2; k >= 0; --k) p.r[k] ^= p.r[k + 1];
    }
    return p;
}

// bank-conflict fold swizzle: GF(2)-linear, maps bit p -> low bit (p mod 3)
__host__ __device__ constexpr unsigned fold(unsigned i) {
    return i ^ (((i >> 3) ^ (i >> 6) ^ (i >> 9)) & 7u);
}

struct SC16 { unsigned v[16]; };
__host__ __device__ constexpr SC16 make_sc(unsigned m0, unsigned m1, unsigned m2, unsigned m3) {
    SC16 s{};
    for (int j = 0; j < 16; j++) {
        unsigned c = 0;
        if (j & 1) c ^= m0;
        if (j & 2) c ^= m1;
        if (j & 4) c ^= m2;
        if (j & 8) c ^= m3;
        s.v[j] = fold(c);
    }
    return s;
}

// ---------------- f32x2 packed helpers (double = opaque 2xf32 carrier) ----------------
__device__ __forceinline__ double pk(float v) {
    double d; asm("mov.b64 %0, {%1, %1};" : "=d"(d) : "f"(v)); return d;
}
__device__ __forceinline__ double pk2(float a, float b) {
    double d; asm("mov.b64 %0, {%1, %2};" : "=d"(d) : "f"(a), "f"(b)); return d;
}
__device__ __forceinline__ double f2fma(double a, double b, double c) {
    double d; asm("fma.rn.f32x2 %0, %1, %2, %3;" : "=d"(d) : "d"(a), "d"(b), "d"(c)); return d;
}
__device__ __forceinline__ double f2mul(double a, double b) {
    double d; asm("mul.rn.f32x2 %0, %1, %2;" : "=d"(d) : "d"(a), "d"(b)); return d;
}
__device__ __forceinline__ double f2add(double a, double b) {
    double d; asm("add.rn.f32x2 %0, %1, %2;" : "=d"(d) : "d"(a), "d"(b)); return d;
}

// out0 = U00*a + U01*b ; out1 = U10*a + U11*b (complex; both f32x2 lanes = 2 batches)
// g layout: [x00,-y00,y00, x01,-y01,y01, x10,-y10,y10, x11,-y11,y11]
__device__ __forceinline__ void apply_pair(const double* g, double2& A, double2& B) {
    double ar = A.x, ai = A.y, br = B.x, bi = B.y;
    double o0r = f2fma(g[0], ar, f2fma(g[1], ai, f2fma(g[3], br, f2mul(g[4], bi))));
    double o0i = f2fma(g[0], ai, f2fma(g[2], ar, f2fma(g[3], bi, f2mul(g[5], br))));
    double o1r = f2fma(g[6], ar, f2fma(g[7], ai, f2fma(g[9], br, f2mul(g[10], bi))));
    double o1i = f2fma(g[6], ai, f2fma(g[8], ar, f2fma(g[9], bi, f2mul(g[11], br))));
    A.x = o0r; A.y = o0i; B.x = o1r; B.y = o1i;
}

// ---------------- 4-wire fused pass: wires W0..W0+3 of layer L ----------------
// Gates stored twice per gate (normal / conjugated); thread picks via parity offset.
template <int L, int W0>
__device__ __forceinline__ void pass4(double2* __restrict__ s,
                                      const double* __restrict__ G, int tid) {
    constexpr Phi P = phi_after(L);
    constexpr int K = NW - 1 - W0;                 // pivots are bits K-3..K (consecutive)
    constexpr unsigned m0 = P.f[K],     m1 = P.f[K - 1];
    constexpr unsigned m2 = P.f[K - 2], m3 = P.f[K - 3];
    constexpr unsigned r0 = P.r[K],     r1 = P.r[K - 1];
    constexpr unsigned r2 = P.r[K - 2], r3 = P.r[K - 3];
    constexpr SC16 SC = make_sc(m0, m1, m2, m3);   // fold-swizzled butterfly offsets

    const unsigned t = tid;
    const unsigned y = ((t >> (K - 3)) << (K + 1)) | (t & ((1u << (K - 3)) - 1u));
    const unsigned sy = fold(y);

    // per-thread gate variant selection (conjugated if logical bit of y is 1)
    const double* gp0 = G + (L * NW + W0) * 24     + ((__popc(r0 & y) & 1) ? 12 : 0);
    const double* gp1 = G + (L * NW + W0 + 1) * 24 + ((__popc(r1 & y) & 1) ? 12 : 0);
    const double* gp2 = G + (L * NW + W0 + 2) * 24 + ((__popc(r2 & y) & 1) ? 12 : 0);
    const double* gp3 = G + (L * NW + W0 + 3) * 24 + ((__popc(r3 & y) & 1) ? 12 : 0);

    double2 v[16];
    #pragma unroll
    for (int j = 0; j < 16; j++) v[j] = s[sy ^ SC.v[j]];

    {   // stage 0: wire W0, pairs (j, j^1)
        double g[12];
        #pragma unroll
        for (int i = 0; i < 12; i++) g[i] = gp0[i];
        #pragma unroll
        for (int j = 0; j < 16; j += 2) apply_pair(g, v[j], v[j + 1]);
    }
    {   // stage 1: wire W0+1, pairs (j, j^2)
        double g[12];
        #pragma unroll
        for (int i = 0; i < 12; i++) g[i] = gp1[i];
        #pragma unroll
        for (int j = 0; j < 16; j++) if (!(j & 2)) apply_pair(g, v[j], v[j ^ 2]);
    }
    {   // stage 2: wire W0+2, pairs (j, j^4)
        double g[12];
        #pragma unroll
        for (int i = 0; i < 12; i++) g[i] = gp2[i];
        #pragma unroll
        for (int j = 0; j < 16; j++) if (!(j & 4)) apply_pair(g, v[j], v[j ^ 4]);
    }
    {   // stage 3: wire W0+3, pairs (j, j^8)
        double g[12];
        #pragma unroll
        for (int i = 0; i < 12; i++) g[i] = gp3[i];
        #pragma unroll
        for (int j = 0; j < 8; j++) apply_pair(g, v[j], v[j + 8]);
    }

    #pragma unroll
    for (int j = 0; j < 16; j++) s[sy ^ SC.v[j]] = v[j];
    __syncthreads();
}

__global__ __launch_bounds__(NT, 2)
void qsim_kernel(const float* __restrict__ state,
                 const float* __restrict__ wts,
                 const float* __restrict__ head_w,
                 const float* __restrict__ head_b,
                 float* __restrict__ out)
{
    extern __shared__ double2 s[];            // DIM amps, fold-swizzled slots, 64 KB
    __shared__ double G2s[NL * NW * 24];      // per gate: 12 normal + 12 conjugated
    __shared__ double wred[NT / 32];

    const int tid = threadIdx.x;
    const int b = blockIdx.x;                 // batches 2b, 2b+1

    // ---- load two real input states into f32x2 lanes (swizzled slots) ----
    {
        const float4* ra = (const float4*)(state + (size_t)(2 * b) * DIM);
        const float4* rb = (const float4*)(state + (size_t)(2 * b + 1) * DIM);
        #pragma unroll
        for (int j = 0; j < DIM / 4 / NT; ++j) {
            int i4 = tid + j * NT;
            float4 xa = ra[i4];
            float4 xb = rb[i4];
            s[fold(4 * i4 + 0)] = make_double2(pk2(xa.x, xb.x), 0.0);
            s[fold(4 * i4 + 1)] = make_double2(pk2(xa.y, xb.y), 0.0);
            s[fold(4 * i4 + 2)] = make_double2(pk2(xa.z, xb.z), 0.0);
            s[fold(4 * i4 + 3)] = make_double2(pk2(xa.w, xb.w), 0.0);
        }
    }

    // ---- build fused U = RZ(c) RY(b) RX(a); store normal + conjugated copies ----
    if (tid < NL * NW) {
        float a  = wts[tid * 3 + 0] * 0.5f;
        float bb = wts[tid * 3 + 1] * 0.5f;
        float c  = wts[tid * 3 + 2] * 0.5f;
        float ca, sa, cb, sb, cc, sc;
        sincosf(a, &sa, &ca);
        sincosf(bb, &sb, &cb);
        sincosf(c, &sc, &cc);
        // M = RY @ RX
        float m00x =  cb * ca, m00y =  sb * sa;
        float m01x = -sb * ca, m01y = -cb * sa;
        float m10x =  sb * ca, m10y = -cb * sa;
        float m11x =  cb * ca, m11y = -sb * sa;
        // row0 *= (cc,-sc); row1 *= (cc,sc)
        float e00x = cc * m00x + sc * m00y, e00y = cc * m00y - sc * m00x;
        float e01x = cc * m01x + sc * m01y, e01y = cc * m01y - sc * m01x;
        float e10x = cc * m10x - sc * m10y, e10y = cc * m10y + sc * m10x;
        float e11x = cc * m11x - sc * m11y, e11y = cc * m11y + sc * m11x;
        double* gp = G2s + tid * 24;
        // normal: c00, c01, c10, c11
        gp[0]  = pk(e00x); gp[1]  = pk(-e00y); gp[2]  = pk(e00y);
        gp[3]  = pk(e01x); gp[4]  = pk(-e01y); gp[5]  = pk(e01y);
        gp[6]  = pk(e10x); gp[7]  = pk(-e10y); gp[8]  = pk(e10y);
        gp[9]  = pk(e11x); gp[10] = pk(-e11y); gp[11] = pk(e11y);
        // conjugated (X G X): c11, c10, c01, c00
        gp[12] = gp[9];  gp[13] = gp[10]; gp[14] = gp[11];
        gp[15] = gp[6];  gp[16] = gp[7];  gp[17] = gp[8];
        gp[18] = gp[3];  gp[19] = gp[4];  gp[20] = gp[5];
        gp[21] = gp[0];  gp[22] = gp[1];  gp[23] = gp[2];
    }
    __syncthreads();

    // ---- 3 layers x 3 fused 4-wire passes; CNOT chains folded into constexpr phi ----
    pass4<0, 0>(s, G2s, tid); pass4<0, 4>(s, G2s, tid); pass4<0, 8>(s, G2s, tid);
    pass4<1, 0>(s, G2s, tid); pass4<1, 4>(s, G2s, tid); pass4<1, 8>(s, G2s, tid);
    pass4<2, 0>(s, G2s, tid); pass4<2, 4>(s, G2s, tid); pass4<2, 8>(s, G2s, tid);

    // ---- fused <Z_w> + linear head: out = sum_i |psi_i|^2 * cf(i) + bias ----
    constexpr Phi PF = phi_after(NL);
    float h[NW];
    #pragma unroll
    for (int w = 0; w < NW; ++w) h[w] = head_w[w];

    double acc = 0.0;
    #pragma unroll
    for (int j = 0; j < DIM / NT; ++j) {
        const unsigned i = tid + j * NT;
        double2 v = s[fold(i)];
        double p2 = f2fma(v.x, v.x, f2mul(v.y, v.y));
        float cf = 0.f;
        #pragma unroll
        for (int w = 0; w < NW; ++w) {
            cf += (__popc(PF.r[NW - 1 - w] & i) & 1) ? -h[w] : h[w];
        }
        acc = f2fma(p2, pk(cf), acc);
    }
    #pragma unroll
    for (int o = 16; o; o >>= 1)
        acc = f2add(acc, __shfl_xor_sync(0xffffffffu, acc, o));
    if ((tid & 31) == 0) wred[tid >> 5] = acc;
    __syncthreads();
    if (tid == 0) {
        double tot = 0.0;
        #pragma unroll
        for (int i = 0; i < NT / 32; ++i) tot = f2add(tot, wred[i]);
        float lo, hi;
        asm("mov.b64 {%0, %1}, %2;" : "=f"(lo), "=f"(hi) : "d"(tot));
        float hb = head_b[0];
        out[2 * b + 0] = lo + hb;
        out[2 * b + 1] = hi + hb;
    }
}

extern "C" void kernel_launch(void* const* d_in, const int* in_sizes, int n_in,
                              void* d_out, int out_size) {
    const float* state  = (const float*)d_in[0];   // (512, 4096) f32
    const float* wts    = (const float*)d_in[1];   // (3, 12, 3)  f32
    const float* head_w = (const float*)d_in[2];   // (1, 12)     f32
    const float* head_b = (const float*)d_in[3];   // (1,)        f32
    float* out = (float*)d_out;                    // (512,)      f32

    const int B = in_sizes[0] / DIM;               // 512
    const int grid = B / 2;                        // 2 batches per block
    const int smem = DIM * sizeof(double2);        // 64 KB dynamic

    cudaFuncSetAttribute(qsim_kernel, cudaFuncAttributeMaxDynamicSharedMemorySize, smem);
    qsim_kernel<<<grid, NT, smem>>>(state, wts, head_w, head_b, out);
}

// round 13
// speedup vs baseline: 2.2901x; 1.0596x over previous
#include <cuda_runtime.h>

#define NW 12
#define NL 3
#define DIM 4096
#define NT 256

// ---------------- compile-time GF(2) bookkeeping ----------------
struct Phi { unsigned f[NW]; unsigned r[NW]; };
__host__ __device__ constexpr Phi phi_after(int l) {
    Phi p{};
    for (int k = 0; k < NW; k++) { p.f[k] = 1u << k; p.r[k] = 1u << k; }
    for (int t = 0; t < l; t++) {
        for (int k = NW - 1; k >= 1; --k) p.f[k] ^= p.f[k - 1];
        for (int k = NW - 2; k >= 0; --k) p.r[k] ^= p.r[k + 1];
    }
    return p;
}
__host__ __device__ constexpr int popc_c(unsigned x) { int n = 0; while (x) { n += x & 1u; x >>= 1; } return n; }

// bank-conflict fold swizzle: GF(2)-linear, maps bit p -> low bit (p mod 3)
__host__ __device__ constexpr unsigned fold(unsigned i) {
    return i ^ (((i >> 3) ^ (i >> 6) ^ (i >> 9)) & 7u);
}

struct C16 { unsigned c[16]; unsigned sc[16]; };
__host__ __device__ constexpr C16 make_c16(unsigned m0, unsigned m1, unsigned m2, unsigned m3) {
    C16 s{};
    for (int j = 0; j < 16; j++) {
        unsigned c = 0;
        if (j & 1) c ^= m0;
        if (j & 2) c ^= m1;
        if (j & 4) c ^= m2;
        if (j & 8) c ^= m3;
        s.c[j] = c;
        s.sc[j] = fold(c);
    }
    return s;
}

// ---------------- f32x2 packed helpers (double = opaque 2xf32 carrier) ----------------
__device__ __forceinline__ double pk(float v) {
    double d; asm("mov.b64 %0, {%1, %1};" : "=d"(d) : "f"(v)); return d;
}
__device__ __forceinline__ double pk2(float a, float b) {
    double d; asm("mov.b64 %0, {%1, %2};" : "=d"(d) : "f"(a), "f"(b)); return d;
}
__device__ __forceinline__ double f2fma(double a, double b, double c) {
    double d; asm("fma.rn.f32x2 %0, %1, %2, %3;" : "=d"(d) : "d"(a), "d"(b), "d"(c)); return d;
}
__device__ __forceinline__ double f2mul(double a, double b) {
    double d; asm("mul.rn.f32x2 %0, %1, %2;" : "=d"(d) : "d"(a), "d"(b)); return d;
}
__device__ __forceinline__ double f2add(double a, double b) {
    double d; asm("add.rn.f32x2 %0, %1, %2;" : "=d"(d) : "d"(a), "d"(b)); return d;
}

// g layout: [x00,-y00,y00, x01,-y01,y01, x10,-y10,y10, x11,-y11,y11]
__device__ __forceinline__ void apply_pair(const double* g, double2& A, double2& B) {
    double ar = A.x, ai = A.y, br = B.x, bi = B.y;
    double o0r = f2fma(g[0], ar, f2fma(g[1], ai, f2fma(g[3], br, f2mul(g[4], bi))));
    double o0i = f2fma(g[0], ai, f2fma(g[2], ar, f2fma(g[3], bi, f2mul(g[5], br))));
    double o1r = f2fma(g[6], ar, f2fma(g[7], ai, f2fma(g[9], br, f2mul(g[10], bi))));
    double o1i = f2fma(g[6], ai, f2fma(g[8], ar, f2fma(g[9], bi, f2mul(g[11], br))));
    A.x = o0r; A.y = o0i; B.x = o1r; B.y = o1i;
}
// inputs purely real (imag = 0): half cost
__device__ __forceinline__ void apply_pair_real(const double* g, double2& A, double2& B) {
    double ar = A.x, br = B.x;
    double o0r = f2fma(g[0], ar, f2mul(g[3], br));
    double o0i = f2fma(g[2], ar, f2mul(g[5], br));
    double o1r = f2fma(g[6], ar, f2mul(g[9], br));
    double o1i = f2fma(g[8], ar, f2mul(g[11], br));
    A.x = o0r; A.y = o0i; B.x = o1r; B.y = o1i;
}

__device__ __forceinline__ void ldg12(const double2* gp2, double* g) {
    #pragma unroll
    for (int i = 0; i < 6; i++) { double2 t = gp2[i]; g[2 * i] = t.x; g[2 * i + 1] = t.y; }
}

// 4 butterfly stages on 16 resident amps
template <bool REAL0>
__device__ __forceinline__ void run_stages(double2* v,
                                           const double2* gp0, const double2* gp1,
                                           const double2* gp2p, const double2* gp3) {
    {   double g[12]; ldg12(gp0, g);
        #pragma unroll
        for (int j = 0; j < 16; j += 2) {
            if (REAL0) apply_pair_real(g, v[j], v[j + 1]);
            else       apply_pair(g, v[j], v[j + 1]);
        }
    }
    {   double g[12]; ldg12(gp1, g);
        #pragma unroll
        for (int j = 0; j < 16; j++) if (!(j & 2)) apply_pair(g, v[j], v[j ^ 2]);
    }
    {   double g[12]; ldg12(gp2p, g);
        #pragma unroll
        for (int j = 0; j < 16; j++) if (!(j & 4)) apply_pair(g, v[j], v[j ^ 4]);
    }
    {   double g[12]; ldg12(gp3, g);
        #pragma unroll
        for (int j = 0; j < 8; j++) apply_pair(g, v[j], v[j + 8]);
    }
}

// middle pass: smem -> stages -> smem -> barrier. All constants function-local constexpr.
template <int L, int W0>
__device__ __forceinline__ void pass_mid(double2* __restrict__ s,
                                         const double2* __restrict__ G, int tid) {
    constexpr Phi P = phi_after(L);
    constexpr int K = NW - 1 - W0;
    constexpr unsigned m0 = P.f[K],     m1 = P.f[K - 1];
    constexpr unsigned m2 = P.f[K - 2], m3 = P.f[K - 3];
    constexpr unsigned win = 0xFu << (K - 3);
    constexpr unsigned ro0 = P.r[K] & ~win,     ro1 = P.r[K - 1] & ~win;
    constexpr unsigned ro2 = P.r[K - 2] & ~win, ro3 = P.r[K - 3] & ~win;
    constexpr C16 SC = make_c16(m0, m1, m2, m3);

    const unsigned t = (unsigned)tid;
    const unsigned y = ((t >> (K - 3)) << (K + 1)) | (t & ((1u << (K - 3)) - 1u));
    const unsigned sy = fold(y);

    const double2* base = G + (L * NW + W0) * 12;
    const double2* g0 = base +      (ro0 ? ((__popc(ro0 & y) & 1) ? 6 : 0) : 0);
    const double2* g1 = base + 12 + (ro1 ? ((__popc(ro1 & y) & 1) ? 6 : 0) : 0);
    const double2* g2 = base + 24 + (ro2 ? ((__popc(ro2 & y) & 1) ? 6 : 0) : 0);
    const double2* g3 = base + 36 + (ro3 ? ((__popc(ro3 & y) & 1) ? 6 : 0) : 0);

    double2 v[16];
    #pragma unroll
    for (int j = 0; j < 16; j++) v[j] = s[sy ^ SC.sc[j]];
    run_stages<false>(v, g0, g1, g2, g3);
    #pragma unroll
    for (int j = 0; j < 16; j++) s[sy ^ SC.sc[j]] = v[j];
    __syncthreads();
}

__global__ __launch_bounds__(NT, 2)
void qsim_kernel(const float* __restrict__ state,
                 const float* __restrict__ wts,
                 const float* __restrict__ head_w,
                 const float* __restrict__ head_b,
                 float* __restrict__ out)
{
    extern __shared__ double2 s[];            // DIM amps, fold-swizzled slots, 64 KB
    __shared__ double2 G2s[NL * NW * 12];     // per gate: 6 d2 normal + 6 d2 conjugated
    __shared__ double wred[NT / 32];

    const int tid = threadIdx.x;
    const int b = blockIdx.x;                 // batches 2b, 2b+1

    // first-pass constants (L=0, W0=0: K=11, y = tid, masks = plain bits, ro = 0)
    constexpr Phi Pf0 = phi_after(0);
    constexpr C16 SC0 = make_c16(Pf0.f[11], Pf0.f[10], Pf0.f[9], Pf0.f[8]);

    // ---- FIRST pass loads straight from GMEM (issued before gate barrier) ----
    double2 v[16];
    {
        const float* ra = state + (size_t)(2 * b) * DIM;
        const float* rb = ra + DIM;
        const unsigned y0 = (unsigned)tid;
        #pragma unroll
        for (int j = 0; j < 16; j++) {
            unsigned idx = y0 ^ SC0.c[j];
            v[j].x = pk2(ra[idx], rb[idx]);
            v[j].y = 0.0;
        }
    }

    // ---- build fused U = RZ(c) RY(b) RX(a); store normal + conjugated (XGX) ----
    if (tid < NL * NW) {
        float a  = wts[tid * 3 + 0] * 0.5f;
        float bb = wts[tid * 3 + 1] * 0.5f;
        float c  = wts[tid * 3 + 2] * 0.5f;
        float ca, sa, cb, sb, cc, sc;
        sincosf(a, &sa, &ca);
        sincosf(bb, &sb, &cb);
        sincosf(c, &sc, &cc);
        float m00x =  cb * ca, m00y =  sb * sa;
        float m01x = -sb * ca, m01y = -cb * sa;
        float m10x =  sb * ca, m10y = -cb * sa;
        float m11x =  cb * ca, m11y = -sb * sa;
        float e00x = cc * m00x + sc * m00y, e00y = cc * m00y - sc * m00x;
        float e01x = cc * m01x + sc * m01y, e01y = cc * m01y - sc * m01x;
        float e10x = cc * m10x - sc * m10y, e10y = cc * m10y + sc * m10x;
        float e11x = cc * m11x - sc * m11y, e11y = cc * m11y + sc * m11x;
        double* gp = (double*)(G2s + tid * 12);
        gp[0]  = pk(e00x); gp[1]  = pk(-e00y); gp[2]  = pk(e00y);
        gp[3]  = pk(e01x); gp[4]  = pk(-e01y); gp[5]  = pk(e01y);
        gp[6]  = pk(e10x); gp[7]  = pk(-e10y); gp[8]  = pk(e10y);
        gp[9]  = pk(e11x); gp[10] = pk(-e11y); gp[11] = pk(e11y);
        // conjugated (X G X): c11, c10, c01, c00
        gp[12] = gp[9];  gp[13] = gp[10]; gp[14] = gp[11];
        gp[15] = gp[6];  gp[16] = gp[7];  gp[17] = gp[8];
        gp[18] = gp[3];  gp[19] = gp[4];  gp[20] = gp[5];
        gp[21] = gp[0];  gp[22] = gp[1];  gp[23] = gp[2];
    }
    __syncthreads();

    // ---- FIRST pass compute (real stage 0) + store; layer 0 has ro == 0 ----
    {
        const unsigned y0 = (unsigned)tid;
        const unsigned sy = fold(y0);
        const double2* base = G2s;            // L=0, W0=0
        run_stages<true>(v, base, base + 12, base + 24, base + 36);
        #pragma unroll
        for (int j = 0; j < 16; j++) s[sy ^ SC0.sc[j]] = v[j];
        __syncthreads();
    }

    // ---- middle passes ----
    pass_mid<0, 4>(s, G2s, tid); pass_mid<0, 8>(s, G2s, tid);
    pass_mid<1, 0>(s, G2s, tid); pass_mid<1, 4>(s, G2s, tid); pass_mid<1, 8>(s, G2s, tid);
    pass_mid<2, 0>(s, G2s, tid); pass_mid<2, 4>(s, G2s, tid);

    // ---- LAST pass (L=2, W0=8): load, stages, epilogue straight from registers ----
    constexpr Phi PL = phi_after(2);
    constexpr int KL = NW - 1 - 8;            // 3
    constexpr unsigned lm0 = PL.f[KL],     lm1 = PL.f[KL - 1];
    constexpr unsigned lm2 = PL.f[KL - 2], lm3 = PL.f[KL - 3];
    constexpr unsigned lwin = 0xFu << (KL - 3);
    constexpr unsigned lro0 = PL.r[KL] & ~lwin,     lro1 = PL.r[KL - 1] & ~lwin;
    constexpr unsigned lro2 = PL.r[KL - 2] & ~lwin, lro3 = PL.r[KL - 3] & ~lwin;
    constexpr C16 SCL = make_c16(lm0, lm1, lm2, lm3);

    unsigned yl;
    {
        const unsigned t = (unsigned)tid;
        yl = ((t >> (KL - 3)) << (KL + 1)) | (t & ((1u << (KL - 3)) - 1u));
        const unsigned sy = fold(yl);
        const double2* base = G2s + (2 * NW + 8) * 12;
        const double2* g0 = base +      (lro0 ? ((__popc(lro0 & yl) & 1) ? 6 : 0) : 0);
        const double2* g1 = base + 12 + (lro1 ? ((__popc(lro1 & yl) & 1) ? 6 : 0) : 0);
        const double2* g2 = base + 24 + (lro2 ? ((__popc(lro2 & yl) & 1) ? 6 : 0) : 0);
        const double2* g3 = base + 36 + (lro3 ? ((__popc(lro3 & yl) & 1) ? 6 : 0) : 0);
        #pragma unroll
        for (int j = 0; j < 16; j++) v[j] = s[sy ^ SCL.sc[j]];
        run_stages<false>(v, g0, g1, g2, g3);
        // no store: v[j] = final amp at index yl ^ SCL.c[j] (thread-local)
    }

    // ---- fused <Z_w> + linear head with constexpr Walsh signs ----
    constexpr Phi PF = phi_after(NL);
    float hw2[NW];
    #pragma unroll
    for (int w = 0; w < NW; ++w) {
        float h = head_w[w];
        hw2[w] = (__popc(PF.r[NW - 1 - w] & yl) & 1) ? -h : h;
    }

    double acc = 0.0;
    #pragma unroll
    for (int j = 0; j < 16; j++) {
        double p2 = f2fma(v[j].x, v[j].x, f2mul(v[j].y, v[j].y));
        float cf = 0.f;
        #pragma unroll
        for (int w = 0; w < NW; ++w) {
            if (popc_c(phi_after(NL).r[NW - 1 - w] & SCL.c[j]) & 1) cf -= hw2[w];
            else                                                     cf += hw2[w];
        }
        acc = f2fma(p2, pk(cf), acc);
    }
    #pragma unroll
    for (int o = 16; o; o >>= 1)
        acc = f2add(acc, __shfl_xor_sync(0xffffffffu, acc, o));
    if ((tid & 31) == 0) wred[tid >> 5] = acc;
    __syncthreads();
    if (tid == 0) {
        double tot = 0.0;
        #pragma unroll
        for (int i = 0; i < NT / 32; ++i) tot = f2add(tot, wred[i]);
        float lo, hi;
        asm("mov.b64 {%0, %1}, %2;" : "=f"(lo), "=f"(hi) : "d"(tot));
        float hb = head_b[0];
        out[2 * b + 0] = lo + hb;
        out[2 * b + 1] = hi + hb;
    }
}

extern "C" void kernel_launch(void* const* d_in, const int* in_sizes, int n_in,
                              void* d_out, int out_size) {
    const float* state  = (const float*)d_in[0];   // (512, 4096) f32
    const float* wts    = (const float*)d_in[1];   // (3, 12, 3)  f32
    const float* head_w = (const float*)d_in[2];   // (1, 12)     f32
    const float* head_b = (const float*)d_in[3];   // (1,)        f32
    float* out = (float*)d_out;                    // (512,)      f32

    const int B = in_sizes[0] / DIM;               // 512
    const int grid = B / 2;                        // 2 batches per block
    const int smem = DIM * sizeof(double2);        // 64 KB dynamic

    cudaFuncSetAttribute(qsim_kernel, cudaFuncAttributeMaxDynamicSharedMemorySize, smem);
    qsim_kernel<<<grid, NT, smem>>>(state, wts, head_w, head_b, out);
}